// round 14
// baseline (speedup 1.0000x reference)
#include <cuda_runtime.h>
#include <cuda_fp16.h>
#include <stdint.h>

// CIN via mma.sync (HMMA): z[(b,d),s] = sum_{h,k} x0*xk*W.
// CTA: 256 threads = 8 warps, 8 batches. warp = (wy: 32 s) x (wx: 4 batches).
// 117 chunks (layer, h); layer-0 weights symmetry-folded upper-triangle so
// chunk h only runs valid k-slabs. Chunks processed in PAIRS per barrier with
// 2 x 32KB double-buffered W staging; B fed by conflict-free lds128
// (row stride 144B: word addr 36*gid+8*tig covers all banks per 8-lane phase).

#define THREADS 256
#define NCHUNK 117
#define NITER 60              // 3 layers x 20 iterations (19 pairs + 1 single)
#define SW128(o) ((o) ^ ((((uint32_t)(o)) >> 3) & 0x70))

// Pre-swizzled f16 W tiles: [chunk][128 s x 64 k] = 16KB each.
__device__ __half WPREP[NCHUNK][8192];

// dynamic smem layout (bytes)
#define OFF_W    0            // 2 x 32768 (each buffer holds a chunk pair)
#define OFF_XKT  65536        // 8 b x 16 d x 72 f16 = 18432 (row stride 144B)
#define OFF_X0   83968        // 8 b x 16 d x 44 u32 (f16x2 dup) = 22528
#define OFF_BIAS 106496       // 384 f32
#define SMEM_TOTAL 108032
#define XKT_B 1152            // f16 per batch (16*72)
#define X0_B 704              // u32 per batch (16*44)

// logical k (0..63) -> physical f16 position within a 64-slot row.
// u32 index = t*8 + ks*2 + r; a 16B lds128 at byte t*32 + p*16 yields
// [b0(ks=2p), b1(ks=2p), b0(ks=2p+1), b1(ks=2p+1)].
__host__ __device__ __forceinline__ int pos64(int k) {
    return ((k & 6) << 3) | ((k >> 2) & 12) | ((k >> 2) & 2) | (k & 1);
}

__device__ __forceinline__ uint32_t smem_u32(const void* p) {
    uint32_t a;
    asm("{ .reg .u64 t; cvta.to.shared.u64 t, %1; cvt.u32.u64 %0, t; }" : "=r"(a) : "l"(p));
    return a;
}
__device__ __forceinline__ uint32_t hmul2(uint32_t a, uint32_t b) {
    uint32_t r;
    asm("mul.rn.f16x2 %0, %1, %2;" : "=r"(r) : "r"(a), "r"(b));
    return r;
}
__device__ __forceinline__ uint4 lds128(uint32_t addr) {
    uint4 v;
    asm volatile("ld.shared.v4.b32 {%0,%1,%2,%3}, [%4];"
                 : "=r"(v.x), "=r"(v.y), "=r"(v.z), "=r"(v.w) : "r"(addr));
    return v;
}
__device__ __forceinline__ uint32_t lds32(uint32_t addr) {
    uint32_t r;
    asm volatile("ld.shared.b32 %0, [%1];" : "=r"(r) : "r"(addr));
    return r;
}
__device__ __forceinline__ void ldsm4(uint32_t* a, uint32_t addr) {
    asm volatile("ldmatrix.sync.aligned.m8n8.x4.shared.b16 {%0,%1,%2,%3}, [%4];"
                 : "=r"(a[0]), "=r"(a[1]), "=r"(a[2]), "=r"(a[3]) : "r"(addr));
}
__device__ __forceinline__ void mma16816(float* c, const uint32_t* a, uint32_t b0, uint32_t b1) {
    asm volatile(
        "mma.sync.aligned.m16n8k16.row.col.f32.f16.f16.f32 "
        "{%0,%1,%2,%3}, {%4,%5,%6,%7}, {%8,%9}, {%0,%1,%2,%3};"
        : "+f"(c[0]), "+f"(c[1]), "+f"(c[2]), "+f"(c[3])
        : "r"(a[0]), "r"(a[1]), "r"(a[2]), "r"(a[3]), "r"(b0), "r"(b1));
}
__device__ __forceinline__ void cp16(uint32_t dst, const void* src) {
    asm volatile("cp.async.ca.shared.global [%0], [%1], 16;" :: "r"(dst), "l"(src) : "memory");
}
__device__ __forceinline__ void cp_commit() {
    asm volatile("cp.async.commit_group;" ::: "memory");
}
template <int N>
__device__ __forceinline__ void cp_wait() {
    asm volatile("cp.async.wait_group %0;" :: "n"(N) : "memory");
}

// ---------------------------------------------------------------------------
// prep: W fp32 [h][k][s] -> per-chunk pre-swizzled f16 smem images.
// Layer 0 symmetry-folded: Wf[h][k] = W[h][k]+W[k][h] (k>h), W[h][h], else 0.
// ---------------------------------------------------------------------------
__global__ void __launch_bounds__(256) prep_w(const float* __restrict__ w0,
                                              const float* __restrict__ w1,
                                              const float* __restrict__ w2) {
    int idx = blockIdx.x * 256 + threadIdx.x;
    if (idx >= NCHUNK * 8192) return;
    int g = idx >> 13;
    int i = idx & 8191;
    int L = g / 39, h = g % 39;
    uint32_t o = SW128((uint32_t)(i * 2));   // involution
    int s = o >> 7;
    int k = (o & 127) >> 1;
    float v = 0.f;
    if (L == 0) {
        if (k < 39 && k >= h) {
            v = w0[(h * 39 + k) * 128 + s];
            if (k > h) v += w0[(k * 39 + h) * 128 + s];
        }
    } else if (L == 1) {
        v = w1[(h * 64 + k) * 128 + s];
    } else {
        v = w2[(h * 64 + k) * 128 + s];
    }
    WPREP[g][i] = __float2half_rn(v);
}

// ---------------------------------------------------------------------------
// main fused kernel
// ---------------------------------------------------------------------------
__global__ void __launch_bounds__(THREADS, 2)
cin_hmma(const float* __restrict__ inputs,
         const float* __restrict__ pb0, const float* __restrict__ pb1,
         const float* __restrict__ pb2, float* __restrict__ out) {
    extern __shared__ char smem[];
    const uint32_t sb = smem_u32(smem);
    const int tid = threadIdx.x;
    const int lane = tid & 31;
    const int wid = tid >> 5;
    const int wy = wid >> 1;          // s-group: s in [wy*32, wy*32+32)
    const int wx = wid & 1;           // batch-group: local batches wx*4..wx*4+3
    const int gid = lane >> 2;        // 0..7  (d row / B n index)
    const int tig = lane & 3;         // 0..3
    const int bstart = blockIdx.x * 8;

    __half* xkt = (__half*)(smem + OFF_XKT);
    uint32_t* x0d = (uint32_t*)(smem + OFF_X0);
    float* sbias = (float*)(smem + OFF_BIAS);

    // prefetch iteration 0 (chunks 0,1) into buf 0
    {
        uint32_t dst = sb + OFF_W + tid * 16;
#pragma unroll
        for (int q = 0; q < 2; ++q) {
            const __half* src = &WPREP[q][tid * 8];
#pragma unroll
            for (int jj = 0; jj < 4; ++jj)
                cp16(dst + q * 16384 + jj * 4096, src + jj * 2048);
        }
        cp_commit();
    }

    // zero xkt (covers layer-0 k pad + stride pad), then fill
    for (int i = tid; i < 4608; i += THREADS) ((uint32_t*)xkt)[i] = 0u;
    __syncthreads();
    for (int i = tid; i < 8 * 624; i += THREADS) {
        int b = i / 624, r = i % 624, h = r / 16, d = r % 16;
        float v = inputs[(size_t)(bstart + b) * 624 + r];
        uint16_t hb = __half_as_ushort(__float2half_rn(v));
        x0d[b * X0_B + d * 44 + h] = (uint32_t)hb * 0x10001u;
        xkt[b * XKT_B + d * 72 + pos64(h)] = __ushort_as_half(hb);
    }
    for (int i = tid; i < 384; i += THREADS)
        sbias[i] = (i < 128) ? pb0[i] : ((i < 256) ? pb1[i - 128] : pb2[i - 256]);

    float C[4][2][2][4];
#pragma unroll
    for (int b = 0; b < 4; ++b)
#pragma unroll
        for (int m = 0; m < 2; ++m)
#pragma unroll
            for (int n = 0; n < 2; ++n)
#pragma unroll
                for (int j = 0; j < 4; ++j) C[b][m][n][j] = 0.f;

    // ldmatrix lane geometry
    const int rowin = (lane & 7) + ((lane >> 3) & 1) * 8;
    const int lrow0 = wy * 32 + rowin;
    const int lcol = ((lane >> 4) & 1) * 16;

    // B lane address: 16B-aligned, conflict-free per 8-lane wavefront
    const uint32_t xk_lane = (uint32_t)(gid * 144 + tig * 32);
    const uint32_t xkt_base = sb + OFF_XKT + wx * 4 * 2304;   // batch stride 2304B
    const uint32_t x0_base = sb + OFF_X0 + wx * 4 * 2816;     // batch stride 2816B

    for (int it = 0; it < NITER; ++it) {
        const int L = it / 20;
        const int j = it - L * 20;
        const int hbase = 2 * j;
        const int ncmp = (j == 19) ? 1 : 2;

        cp_wait<0>();
        __syncthreads();   // current buffer ready; prior buffer's reads retired

        // prefetch next iteration's pair into the other buffer (safe after sync)
        if (it + 1 < NITER) {
            int Ln = (it + 1) / 20, jn = (it + 1) - Ln * 20;
            int gb = Ln * 39 + jn * 2;
            int nn = (jn == 19) ? 1 : 2;
            uint32_t dst = sb + OFF_W + ((it + 1) & 1) * 32768 + tid * 16;
            for (int q = 0; q < nn; ++q) {
                const __half* src = &WPREP[gb + q][tid * 8];
#pragma unroll
                for (int jj = 0; jj < 4; ++jj)
                    cp16(dst + q * 16384 + jj * 4096, src + jj * 2048);
            }
        }
        cp_commit();

        const uint32_t bufbase = sb + OFF_W + (it & 1) * 32768;

        for (int cc = 0; cc < ncmp; ++cc) {
            const int h = hbase + cc;            // chunk index within layer
            const uint32_t wbase = bufbase + cc * 16384;
            const int klo = (L == 0) ? (h >> 4) : 0;

            // x0 f16x2 dups for this chunk (x0 smem is immutable after init)
            uint32_t x0lo[4], x0hi[4];
#pragma unroll
            for (int bb = 0; bb < 4; ++bb) {
                uint32_t xa = x0_base + (bb * X0_B + gid * 44 + h) * 4;
                x0lo[bb] = lds32(xa);
                x0hi[bb] = lds32(xa + 1408);
            }

#pragma unroll
            for (int p = 0; p < 2; ++p) {
                bool run0, run1;
                if (L == 0) {
                    if (p == 0 && klo == 2) continue;   // slabs 0,1 all-zero
                    run0 = (p == 1) || (klo == 0);      // ks=0 valid only if klo==0
                    run1 = (p == 0);                    // ks=3 is pad in layer 0
                } else {
                    run0 = true; run1 = true;
                }
                const int ks0 = 2 * p, ks1 = 2 * p + 1;

                uint32_t A0[4], A1[4], A2[4], A3[4];
                if (run0) {
                    ldsm4(A0, wbase + SW128((uint32_t)(lrow0 * 128 + ks0 * 32 + lcol)));
                    ldsm4(A1, wbase + SW128((uint32_t)((lrow0 + 16) * 128 + ks0 * 32 + lcol)));
                }
                if (run1) {
                    ldsm4(A2, wbase + SW128((uint32_t)(lrow0 * 128 + ks1 * 32 + lcol)));
                    ldsm4(A3, wbase + SW128((uint32_t)((lrow0 + 16) * 128 + ks1 * 32 + lcol)));
                }
#pragma unroll
                for (int bb = 0; bb < 4; ++bb) {
                    const uint32_t xb = xkt_base + bb * 2304 + xk_lane + p * 16;
                    uint4 rlo = lds128(xb);          // d-row gid
                    uint4 rhi = lds128(xb + 1152);   // d-row gid+8
                    if (run0) {
                        uint32_t b00 = hmul2(rlo.x, x0lo[bb]);
                        uint32_t b01 = hmul2(rlo.y, x0lo[bb]);
                        uint32_t b10 = hmul2(rhi.x, x0hi[bb]);
                        uint32_t b11 = hmul2(rhi.y, x0hi[bb]);
                        mma16816(C[bb][0][0], A0, b00, b01);
                        mma16816(C[bb][0][1], A0, b10, b11);
                        mma16816(C[bb][1][0], A1, b00, b01);
                        mma16816(C[bb][1][1], A1, b10, b11);
                    }
                    if (run1) {
                        uint32_t b00 = hmul2(rlo.z, x0lo[bb]);
                        uint32_t b01 = hmul2(rlo.w, x0lo[bb]);
                        uint32_t b10 = hmul2(rhi.z, x0hi[bb]);
                        uint32_t b11 = hmul2(rhi.w, x0hi[bb]);
                        mma16816(C[bb][0][0], A2, b00, b01);
                        mma16816(C[bb][0][1], A2, b10, b11);
                        mma16816(C[bb][1][0], A3, b00, b01);
                        mma16816(C[bb][1][1], A3, b10, b11);
                    }
                }
            }
        }

        if (j == 19) {
            // ---- layer epilogue ----
            __syncthreads();   // all MMA reads of xkt done before overwrite
#pragma unroll
            for (int bb = 0; bb < 4; ++bb) {
                float* outp = out + (size_t)(bstart + wx * 4 + bb) * 256;
                __half* xkb = xkt + (wx * 4 + bb) * XKT_B;
#pragma unroll
                for (int m = 0; m < 2; ++m) {
                    const int s_r = wy * 32 + m * 16 + gid;      // and s_r + 8
                    const float b_r = sbias[L * 128 + s_r];
                    const float b_r8 = sbias[L * 128 + s_r + 8];
                    float vr = 0.f, vr8 = 0.f;
                    const int pos = pos64(s_r & 63);
                    const int pos8 = pos64((s_r + 8) & 63);
#pragma unroll
                    for (int n = 0; n < 2; ++n)
#pragma unroll
                        for (int jj = 0; jj < 2; ++jj) {
                            const int d = 2 * tig + jj + n * 8;
                            float z = fmaxf(C[bb][m][n][jj] + b_r, 0.f);
                            float z8 = fmaxf(C[bb][m][n][2 + jj] + b_r8, 0.f);
                            if (L < 2 && wy < 2) {
                                xkb[d * 72 + pos] = __float2half_rn(z);
                                xkb[d * 72 + pos8] = __float2half_rn(z8);
                            }
                            vr += z;
                            vr8 += z8;
                        }
                    vr += __shfl_xor_sync(0xffffffffu, vr, 1);
                    vr += __shfl_xor_sync(0xffffffffu, vr, 2);
                    vr8 += __shfl_xor_sync(0xffffffffu, vr8, 1);
                    vr8 += __shfl_xor_sync(0xffffffffu, vr8, 2);
                    if (tig == 0) {
                        if (L == 2) {
                            outp[128 + s_r] = vr;
                            outp[128 + s_r + 8] = vr8;
                        } else if (wy >= 2) {
                            outp[L * 64 + s_r - 64] = vr;
                            outp[L * 64 + s_r - 64 + 8] = vr8;
                        }
                    }
                }
#pragma unroll
                for (int m = 0; m < 2; ++m)
#pragma unroll
                    for (int n = 0; n < 2; ++n)
#pragma unroll
                        for (int jj = 0; jj < 4; ++jj) C[bb][m][n][jj] = 0.f;
            }
            __syncthreads();   // new xkt visible before next layer's loads
        }
    }
}

extern "C" void kernel_launch(void* const* d_in, const int* in_sizes, int n_in,
                              void* d_out, int out_size) {
    const float *inp = nullptr, *w0 = nullptr, *w1 = nullptr, *w2 = nullptr;
    const float *pb0 = nullptr, *pb1 = nullptr, *pb2 = nullptr;
    for (int i = 0; i < n_in; ++i) {
        const float* p = (const float*)d_in[i];
        int s = in_sizes[i];
        if (s == 2048 * 39 * 16) {
            inp = p;
        } else if (s == 39 * 39 * 128) {
            w0 = p;
        } else if (s == 39 * 64 * 128) {
            if (!w1) w1 = p; else w2 = p;
        } else if (s == 128) {
            if (!pb0) pb0 = p; else if (!pb1) pb1 = p; else pb2 = p;
        }
    }
    cudaFuncSetAttribute(cin_hmma, cudaFuncAttributeMaxDynamicSharedMemorySize, SMEM_TOTAL);
    prep_w<<<(NCHUNK * 8192 + 255) / 256, 256>>>(w0, w1, w2);
    cin_hmma<<<256, THREADS, SMEM_TOTAL>>>(inp, pb0, pb1, pb2, (float*)d_out);
}